// round 15
// baseline (speedup 1.0000x reference)
#include <cuda_runtime.h>
#include <cuda_fp16.h>
#include <cstdint>
#include <math.h>

// GPT forward: B=4, T=512, L=12, C=1024, H=16, HD=64, F=4096, V=32000
#define Bn   4
#define Tn   512
#define Ln   12
#define Cn   1024
#define Hn   16
#define HDn  64
#define Fn   4096
#define Vn   32000
#define BT   (Bn * Tn)          // 2048
#define C3   (3 * Cn)           // 3072

// ---------------- static scratch (no allocations allowed) ----------------
__device__ float  g_x  [BT * Cn];            // residual stream (fp32)
__device__ __half g_xn [BT * Cn];
__device__ __half g_qkv[BT * C3];
__device__ __half g_y  [BT * Cn];
__device__ __half g_h  [BT * Fn];
__device__ __half g_wqkvH[(size_t)Ln * Cn * C3];
__device__ __half g_woH[Ln * Cn * Cn];
__device__ __half g_w1H[Ln * Cn * Fn];
__device__ __half g_w2H[Ln * Fn * Cn];
__device__ __half g_wlmH[(size_t)Vn * Cn];

__device__ __forceinline__ uint32_t smem_u32(const void* p) {
    uint32_t a;
    asm("{ .reg .u64 t; cvta.to.shared.u64 t, %1; cvt.u32.u64 %0, t; }"
        : "=r"(a) : "l"(p));
    return a;
}
__device__ __forceinline__ void cp16(void* s, const void* g) {
    asm volatile("cp.async.cg.shared.global [%0], [%1], 16;"
                 :: "r"(smem_u32(s)), "l"(g) : "memory");
}
#define CP_COMMIT() asm volatile("cp.async.commit_group;" ::: "memory")
#define CP_WAIT1()  asm volatile("cp.async.wait_group 1;" ::: "memory")
#define CP_WAIT0()  asm volatile("cp.async.wait_group 0;" ::: "memory")

#define MMA_F16(acc, a, b0, b1) \
    asm volatile( \
        "mma.sync.aligned.m16n8k16.row.col.f32.f16.f16.f32 " \
        "{%0,%1,%2,%3}, {%4,%5,%6,%7}, {%8,%9}, {%0,%1,%2,%3};" \
        : "+f"((acc)[0]), "+f"((acc)[1]), "+f"((acc)[2]), "+f"((acc)[3]) \
        : "r"((a)[0]), "r"((a)[1]), "r"((a)[2]), "r"((a)[3]), \
          "r"(b0), "r"(b1))

// ---------------- one-shot weight rounding / packing to fp16 -------------
#define N_QKVO (Ln * Cn * Cn)
#define N_FF   (Ln * Cn * Fn)
#define N_LM   ((size_t)Vn * Cn)

__global__ void round_weights(const float* wq, const float* wk, const float* wv,
                              const float* wo, const float* w1, const float* w2,
                              const float* wlm,
                              __half* wqkvH, __half* woH,
                              __half* w1H, __half* w2H, __half* wlmH) {
    const float* in; __half* out; size_t n;
    int sel = -1;
    switch (blockIdx.y) {
        case 0: in = wq;  out = wqkvH; n = N_QKVO; sel = 0; break;
        case 1: in = wk;  out = wqkvH; n = N_QKVO; sel = 1; break;
        case 2: in = wv;  out = wqkvH; n = N_QKVO; sel = 2; break;
        case 3: in = wo;  out = woH;  n = N_QKVO; break;
        case 4: in = w1;  out = w1H;  n = N_FF;   break;
        case 5: in = w2;  out = w2H;  n = N_FF;   break;
        default: in = wlm; out = wlmH; n = N_LM;  break;
    }
    size_t i = ((size_t)blockIdx.x * 256 + threadIdx.x) * 8;
    if (i >= n) return;
    float4 v0 = *(const float4*)(in + i);
    float4 v1 = *(const float4*)(in + i + 4);
    __half2 h[4];
    h[0] = __floats2half2_rn(v0.x, v0.y);
    h[1] = __floats2half2_rn(v0.z, v0.w);
    h[2] = __floats2half2_rn(v1.x, v1.y);
    h[3] = __floats2half2_rn(v1.z, v1.w);
    size_t oi = i;
    if (sel >= 0) {
        size_t l = i / (Cn * Cn);
        size_t rem = i - l * Cn * Cn;
        size_t kk = rem / Cn, nn = rem % Cn;
        oi = (l * Cn + kk) * C3 + (size_t)sel * Cn + nn;
    }
    *(uint4*)(out + oi) = *(uint4*)h;
}

// ---------------- embedding ----------------
__global__ void embed_kernel(const int* __restrict__ idx,
                             const float* __restrict__ tok,
                             const float* __restrict__ pos,
                             float* __restrict__ x) {
    int row = blockIdx.x;
    int t = row & (Tn - 1);
    int token = idx[row];
    const float* tp = tok + (size_t)token * Cn;
    const float* pp = pos + (size_t)t * Cn;
    float* xp = x + (size_t)row * Cn;
    for (int c = threadIdx.x; c < Cn; c += 256)
        xp[c] = tp[c] + pp[c];
}

// ---------------- layernorm: warp per row, shuffle reductions ------------
__global__ __launch_bounds__(256)
void ln_kernel(const float* __restrict__ in,
               const float* __restrict__ g,
               const float* __restrict__ b,
               __half* __restrict__ out) {
    const int lane = threadIdx.x & 31;
    const int row = blockIdx.x * 8 + (threadIdx.x >> 5);
    const float* p = in + (size_t)row * Cn;
    float v[32];
    float s = 0.f, sq = 0.f;
    #pragma unroll
    for (int k = 0; k < 32; k++) {
        v[k] = p[lane + 32 * k];
        s += v[k]; sq += v[k] * v[k];
    }
    #pragma unroll
    for (int o = 16; o > 0; o >>= 1) {
        s  += __shfl_xor_sync(0xffffffffu, s,  o);
        sq += __shfl_xor_sync(0xffffffffu, sq, o);
    }
    const float mean = s * (1.f / Cn);
    const float var  = sq * (1.f / Cn) - mean * mean;
    const float inv  = rsqrtf(var + 1e-5f);
    __half* op = out + (size_t)row * Cn;
    #pragma unroll
    for (int k = 0; k < 32; k++) {
        int c = lane + 32 * k;
        op[c] = __float2half((v[k] - mean) * inv * g[c] + b[c]);
    }
}

// ---------------- fp16 mma GEMM: CTA 128x128, 4 warps, BK=64, 3-stage ----
// SAFE pipeline: prologue stages 0,1; wait_group 1; compute it%3; prefetch
// (it+2)%3 (readers drained by this iteration's barrier).
#define APAD2 72
#define BPADh 136
#define ASZ2  (128 * APAD2)
#define BSZ2  (64 * BPADh)
#define STAGE2 (ASZ2 + BSZ2)
#define GEMM_SMEM (3 * STAGE2 * 2)       // 107520 bytes

template<bool RELU, bool OUTH, bool ATOMIC>
__global__ __launch_bounds__(128, 2)
void gemm_h(const __half* __restrict__ A, const __half* __restrict__ B,
            const float* __restrict__ bias, const float* __restrict__ res,
            void* __restrict__ Cout, int N, int K) {
    extern __shared__ __half smh[];
    const int tid = threadIdx.x;
    const int lane = tid & 31, wid = tid >> 5;
    const int warp_m = (wid & 1) << 6;
    const int warp_n = (wid >> 1) << 6;
    const int m0 = blockIdx.y * 128;
    const int n0 = blockIdx.x * 128;
    const int Ksub = K / gridDim.z;
    const int koff = blockIdx.z * Ksub;

    const __half* aptr[8]; int saoff[8];
    const __half* bptr[8]; int sboff[8];
    #pragma unroll
    for (int j = 0; j < 8; j++) {
        int ia = j * 128 + tid;
        int ar = ia >> 3, ac = (ia & 7) << 3;
        aptr[j] = A + (size_t)(m0 + ar) * K + koff + ac;
        saoff[j] = ar * APAD2 + ac;
        int bk = ia >> 4, bc = (ia & 15) << 3;
        bptr[j] = B + (size_t)(koff + bk) * N + n0 + bc;
        sboff[j] = bk * BPADh + bc;
    }

    const int nk = Ksub >> 6;

    #pragma unroll
    for (int s = 0; s < 2; s++) {
        __half* As = smh + s * STAGE2;
        __half* Bs = As + ASZ2;
        const int kk = s << 6;
        #pragma unroll
        for (int j = 0; j < 8; j++) {
            cp16(As + saoff[j], aptr[j] + kk);
            cp16(Bs + sboff[j], bptr[j] + (size_t)kk * N);
        }
        CP_COMMIT();
    }

    float acc[4][8][4];
    #pragma unroll
    for (int mi = 0; mi < 4; mi++)
        #pragma unroll
        for (int ni = 0; ni < 8; ni++)
            #pragma unroll
            for (int r = 0; r < 4; r++) acc[mi][ni][r] = 0.f;

    const int a_i = lane >> 3;
    const int arow_lane = ((a_i & 1) << 3) + (lane & 7);
    const int acol_lane = (a_i >> 1) << 3;
    const int vb_k = (lane & 7) + ((lane >> 3) & 1) * 8;
    const int vb_n = ((lane >> 4) & 1) * 8;

    int rs = 0, ws = 2;
    for (int it = 0; it < nk; ++it) {
        if (it + 1 < nk) CP_WAIT1(); else CP_WAIT0();
        __syncthreads();

        const __half* Ac = smh + rs * STAGE2;
        const __half* Bc = Ac + ASZ2;
        #pragma unroll
        for (int ks = 0; ks < 4; ks++) {
            const int kb = ks << 4;
            uint32_t af[4][4];
            #pragma unroll
            for (int mi = 0; mi < 4; mi++) {
                int row = warp_m + mi * 16 + arow_lane;
                uint32_t ad = smem_u32(Ac + row * APAD2 + kb + acol_lane);
                asm volatile("ldmatrix.sync.aligned.m8n8.x4.shared.b16 "
                             "{%0,%1,%2,%3}, [%4];"
                             : "=r"(af[mi][0]), "=r"(af[mi][1]),
                               "=r"(af[mi][2]), "=r"(af[mi][3]) : "r"(ad));
            }
            #pragma unroll
            for (int nj = 0; nj < 4; nj++) {
                uint32_t bv[4];
                uint32_t bd = smem_u32(Bc + (kb + vb_k) * BPADh
                                       + warp_n + nj * 16 + vb_n);
                asm volatile("ldmatrix.sync.aligned.m8n8.x4.trans.shared.b16 "
                             "{%0,%1,%2,%3}, [%4];"
                             : "=r"(bv[0]), "=r"(bv[1]), "=r"(bv[2]), "=r"(bv[3])
                             : "r"(bd));
                #pragma unroll
                for (int mi = 0; mi < 4; mi++) {
                    MMA_F16(acc[mi][nj * 2],     af[mi], bv[0], bv[1]);
                    MMA_F16(acc[mi][nj * 2 + 1], af[mi], bv[2], bv[3]);
                }
            }
        }

        if (it + 2 < nk) {
            const int kk = (it + 2) << 6;
            __half* As = smh + ws * STAGE2;
            __half* Bs = As + ASZ2;
            #pragma unroll
            for (int j = 0; j < 8; j++) {
                cp16(As + saoff[j], aptr[j] + kk);
                cp16(Bs + sboff[j], bptr[j] + (size_t)kk * N);
            }
        }
        CP_COMMIT();

        rs = (rs == 2) ? 0 : rs + 1;
        ws = (ws == 2) ? 0 : ws + 1;
    }

    const bool addb = (bias != nullptr) && (!ATOMIC || blockIdx.z == 0);
    #pragma unroll
    for (int mi = 0; mi < 4; mi++) {
        int row = m0 + warp_m + mi * 16 + (lane >> 2);
        #pragma unroll
        for (int ni = 0; ni < 8; ni++) {
            int col = n0 + warp_n + ni * 8 + ((lane & 3) << 1);
            float v0 = acc[mi][ni][0], v1 = acc[mi][ni][1];
            float v2 = acc[mi][ni][2], v3 = acc[mi][ni][3];
            if (addb) {
                float b0 = bias[col], b1 = bias[col + 1];
                v0 += b0; v1 += b1; v2 += b0; v3 += b1;
            }
            if (RELU) {
                v0 = fmaxf(v0, 0.f); v1 = fmaxf(v1, 0.f);
                v2 = fmaxf(v2, 0.f); v3 = fmaxf(v3, 0.f);
            }
            if (ATOMIC) {
                float* Cp = (float*)Cout;
                atomicAdd(Cp + (size_t)row * N + col,       v0);
                atomicAdd(Cp + (size_t)row * N + col + 1,   v1);
                atomicAdd(Cp + (size_t)(row + 8) * N + col,     v2);
                atomicAdd(Cp + (size_t)(row + 8) * N + col + 1, v3);
            } else if (OUTH) {
                __half* Cp = (__half*)Cout;
                *(__half2*)(Cp + (size_t)row * N + col) = __floats2half2_rn(v0, v1);
                *(__half2*)(Cp + (size_t)(row + 8) * N + col) = __floats2half2_rn(v2, v3);
            } else {
                float* Cp = (float*)Cout;
                if (res) {
                    const float2 r0 = *(const float2*)(res + (size_t)row * N + col);
                    const float2 r1 = *(const float2*)(res + (size_t)(row + 8) * N + col);
                    v0 += r0.x; v1 += r0.y; v2 += r1.x; v3 += r1.y;
                }
                *(float2*)(Cp + (size_t)row * N + col) = make_float2(v0, v1);
                *(float2*)(Cp + (size_t)(row + 8) * N + col) = make_float2(v2, v3);
            }
        }
    }
}

// ---------------- tensor-core flash attention: 128 t-rows per block ------
// 256 threads / 8 warps, 16 rows per warp (same per-warp math as before:
// per-row summation order identical -> bitwise-same output).
#define QP 72
#define ATTN_SMEM ((128 + 4 * 64) * QP * 2)   // 55296 bytes (dynamic)

__global__ __launch_bounds__(256)
void attn_mma(const __half* __restrict__ qkv, __half* __restrict__ y) {
    extern __shared__ __half asm_h[];
    __half* sQ  = asm_h;                       // 128 x QP
    __half* sK0 = sQ  + 128 * QP;
    __half* sK1 = sK0 + 64 * QP;
    __half* sV0 = sK1 + 64 * QP;
    __half* sV1 = sV0 + 64 * QP;
    __half* sKb[2] = { sK0, sK1 };
    __half* sVb[2] = { sV0, sV1 };

    const int bid = blockIdx.x, h = blockIdx.y, b = blockIdx.z;
    const int tid = threadIdx.x, lane = tid & 31, wid = tid >> 5;
    const size_t base = (size_t)b * Tn * C3 + (size_t)h * HDn;
    const int t0 = bid * 128;
    const int ntiles = 2 * bid + 2;            // K tiles 0..2*bid+1

    // stage Q (128 rows x 64 halves = 1024 x16B; 256 thr -> 4 each)
    #pragma unroll
    for (int j = 0; j < 4; j++) {
        int i = j * 256 + tid;
        int r = i >> 3, c = (i & 7) << 3;
        cp16(sQ + r * QP + c, qkv + base + (size_t)(t0 + r) * C3 + c);
    }
    // prefetch K/V tile 0 (512 x16B each; 2 per thread)
    #pragma unroll
    for (int j = 0; j < 2; j++) {
        int i = j * 256 + tid;
        int r = i >> 3, c = (i & 7) << 3;
        size_t g = base + (size_t)r * C3 + c;
        cp16(sK0 + r * QP + c, qkv + g + Cn);
        cp16(sV0 + r * QP + c, qkv + g + 2 * Cn);
    }
    CP_COMMIT();
    CP_WAIT0();
    __syncthreads();

    const int a_i = lane >> 3;
    const int arow = ((a_i & 1) << 3) + (lane & 7);
    const int acol = (a_i >> 1) << 3;
    uint32_t qA[4][4];
    #pragma unroll
    for (int kt = 0; kt < 4; kt++) {
        uint32_t ad = smem_u32(sQ + (wid * 16 + arow) * QP + kt * 16 + acol);
        asm volatile("ldmatrix.sync.aligned.m8n8.x4.shared.b16 "
                     "{%0,%1,%2,%3}, [%4];"
                     : "=r"(qA[kt][0]), "=r"(qA[kt][1]),
                       "=r"(qA[kt][2]), "=r"(qA[kt][3]) : "r"(ad));
    }

    float o[8][4];
    #pragma unroll
    for (int ni = 0; ni < 8; ni++)
        #pragma unroll
        for (int r = 0; r < 4; r++) o[ni][r] = 0.f;
    float m0 = -1e30f, m1 = -1e30f, l0 = 0.f, l1 = 0.f;

    const int c_lane = (lane & 3) << 1;
    const int tr0 = t0 + wid * 16 + (lane >> 2);   // rows tr0, tr0+8

    const int kb_n = (lane & 7) + ((lane >> 4) & 1) * 8;
    const int kb_k = ((lane >> 3) & 1) * 8;
    const int vb_k = (lane & 7) + ((lane >> 3) & 1) * 8;
    const int vb_n = ((lane >> 4) & 1) * 8;

    for (int st = 0; st < ntiles; ++st) {
        CP_WAIT0();
        __syncthreads();

        if (st + 1 < ntiles) {
            const int s1 = (st + 1) * 64;
            __half* dK = sKb[(st + 1) & 1];
            __half* dV = sVb[(st + 1) & 1];
            #pragma unroll
            for (int j = 0; j < 2; j++) {
                int i = j * 256 + tid;
                int r = i >> 3, c = (i & 7) << 3;
                size_t g = base + (size_t)(s1 + r) * C3 + c;
                cp16(dK + r * QP + c, qkv + g + Cn);
                cp16(dV + r * QP + c, qkv + g + 2 * Cn);
            }
        }
        CP_COMMIT();

        const __half* cK = sKb[st & 1];
        const __half* cV = sVb[st & 1];
        const int s0 = st * 64;

        float s[8][4];
        #pragma unroll
        for (int ni = 0; ni < 8; ni++)
            #pragma unroll
            for (int r = 0; r < 4; r++) s[ni][r] = 0.f;

        #pragma unroll
        for (int kt = 0; kt < 4; kt++) {
            #pragma unroll
            for (int nj = 0; nj < 4; nj++) {
                uint32_t bf[4];
                uint32_t bd = smem_u32(cK + (nj * 16 + kb_n) * QP + kt * 16 + kb_k);
                asm volatile("ldmatrix.sync.aligned.m8n8.x4.shared.b16 "
                             "{%0,%1,%2,%3}, [%4];"
                             : "=r"(bf[0]), "=r"(bf[1]), "=r"(bf[2]), "=r"(bf[3])
                             : "r"(bd));
                MMA_F16(s[nj * 2],     qA[kt], bf[0], bf[1]);
                MMA_F16(s[nj * 2 + 1], qA[kt], bf[2], bf[3]);
            }
        }

        #pragma unroll
        for (int ni = 0; ni < 8; ni++) {
            s[ni][0] *= 0.125f; s[ni][1] *= 0.125f;
            s[ni][2] *= 0.125f; s[ni][3] *= 0.125f;
        }
        if (s0 + 63 > t0) {       // tile overlaps/after block start: mask
            #pragma unroll
            for (int ni = 0; ni < 8; ni++) {
                int sc = s0 + ni * 8 + c_lane;
                if (sc     > tr0)     s[ni][0] = -1e30f;
                if (sc + 1 > tr0)     s[ni][1] = -1e30f;
                if (sc     > tr0 + 8) s[ni][2] = -1e30f;
                if (sc + 1 > tr0 + 8) s[ni][3] = -1e30f;
            }
        }

        float tm0 = m0, tm1 = m1;
        #pragma unroll
        for (int ni = 0; ni < 8; ni++) {
            tm0 = fmaxf(tm0, fmaxf(s[ni][0], s[ni][1]));
            tm1 = fmaxf(tm1, fmaxf(s[ni][2], s[ni][3]));
        }
        tm0 = fmaxf(tm0, __shfl_xor_sync(0xffffffffu, tm0, 1));
        tm0 = fmaxf(tm0, __shfl_xor_sync(0xffffffffu, tm0, 2));
        tm1 = fmaxf(tm1, __shfl_xor_sync(0xffffffffu, tm1, 1));
        tm1 = fmaxf(tm1, __shfl_xor_sync(0xffffffffu, tm1, 2));
        if (tm0 > m0) {
            float sc_ = __expf(m0 - tm0);
            l0 *= sc_;
            #pragma unroll
            for (int ni = 0; ni < 8; ni++) { o[ni][0] *= sc_; o[ni][1] *= sc_; }
            m0 = tm0;
        }
        if (tm1 > m1) {
            float sc_ = __expf(m1 - tm1);
            l1 *= sc_;
            #pragma unroll
            for (int ni = 0; ni < 8; ni++) { o[ni][2] *= sc_; o[ni][3] *= sc_; }
            m1 = tm1;
        }
        #pragma unroll
        for (int ni = 0; ni < 8; ni++) {
            s[ni][0] = __expf(s[ni][0] - m0);
            s[ni][1] = __expf(s[ni][1] - m0);
            s[ni][2] = __expf(s[ni][2] - m1);
            s[ni][3] = __expf(s[ni][3] - m1);
            l0 += s[ni][0] + s[ni][1];
            l1 += s[ni][2] + s[ni][3];
        }

        uint32_t aP[4][4];
        #pragma unroll
        for (int kt = 0; kt < 4; kt++) {
            __half2 h0 = __floats2half2_rn(s[2 * kt][0],     s[2 * kt][1]);
            __half2 h1 = __floats2half2_rn(s[2 * kt][2],     s[2 * kt][3]);
            __half2 h2v = __floats2half2_rn(s[2 * kt + 1][0], s[2 * kt + 1][1]);
            __half2 h3 = __floats2half2_rn(s[2 * kt + 1][2], s[2 * kt + 1][3]);
            aP[kt][0] = *(uint32_t*)&h0;
            aP[kt][1] = *(uint32_t*)&h1;
            aP[kt][2] = *(uint32_t*)&h2v;
            aP[kt][3] = *(uint32_t*)&h3;
        }

        #pragma unroll
        for (int kt = 0; kt < 4; kt++) {
            #pragma unroll
            for (int nj = 0; nj < 4; nj++) {
                uint32_t bv[4];
                uint32_t bd = smem_u32(cV + (kt * 16 + vb_k) * QP + nj * 16 + vb_n);
                asm volatile("ldmatrix.sync.aligned.m8n8.x4.trans.shared.b16 "
                             "{%0,%1,%2,%3}, [%4];"
                             : "=r"(bv[0]), "=r"(bv[1]), "=r"(bv[2]), "=r"(bv[3])
                             : "r"(bd));
                MMA_F16(o[nj * 2],     aP[kt], bv[0], bv[1]);
                MMA_F16(o[nj * 2 + 1], aP[kt], bv[2], bv[3]);
            }
        }
    }

    l0 += __shfl_xor_sync(0xffffffffu, l0, 1);
    l0 += __shfl_xor_sync(0xffffffffu, l0, 2);
    l1 += __shfl_xor_sync(0xffffffffu, l1, 1);
    l1 += __shfl_xor_sync(0xffffffffu, l1, 2);
    const float inv0 = 1.f / l0, inv1 = 1.f / l1;
    const size_t ybase = (size_t)b * Tn * Cn + (size_t)h * HDn;
    #pragma unroll
    for (int ni = 0; ni < 8; ni++) {
        int d = ni * 8 + c_lane;
        *(__half2*)(y + ybase + (size_t)tr0 * Cn + d) =
            __floats2half2_rn(o[ni][0] * inv0, o[ni][1] * inv0);
        *(__half2*)(y + ybase + (size_t)(tr0 + 8) * Cn + d) =
            __floats2half2_rn(o[ni][2] * inv1, o[ni][3] * inv1);
    }
}

// ---------------- launch ----------------
extern "C" void kernel_launch(void* const* d_in, const int* in_sizes, int n_in,
                              void* d_out, int out_size) {
    const int*   idx   = (const int*)  d_in[0];
    const float* tok   = (const float*)d_in[1];
    const float* pos   = (const float*)d_in[2];
    const float* wq    = (const float*)d_in[3];
    const float* wk    = (const float*)d_in[4];
    const float* wv    = (const float*)d_in[5];
    const float* wo    = (const float*)d_in[6];
    const float* bo    = (const float*)d_in[7];
    const float* ln1g  = (const float*)d_in[8];
    const float* ln1b  = (const float*)d_in[9];
    const float* ln2g  = (const float*)d_in[10];
    const float* ln2b  = (const float*)d_in[11];
    const float* w1    = (const float*)d_in[12];
    const float* b1    = (const float*)d_in[13];
    const float* w2    = (const float*)d_in[14];
    const float* b2    = (const float*)d_in[15];
    const float* lnfg  = (const float*)d_in[16];
    const float* lnfb  = (const float*)d_in[17];
    const float* wlm   = (const float*)d_in[18];
    float* out = (float*)d_out;

    float *x;
    __half *xn, *qkv, *y, *h;
    __half *wqkvH, *woH, *w1H, *w2H, *wlmH;
    cudaGetSymbolAddress((void**)&x,   g_x);
    cudaGetSymbolAddress((void**)&xn,  g_xn);
    cudaGetSymbolAddress((void**)&qkv, g_qkv);
    cudaGetSymbolAddress((void**)&y,   g_y);
    cudaGetSymbolAddress((void**)&h,   g_h);
    cudaGetSymbolAddress((void**)&wqkvH, g_wqkvH);
    cudaGetSymbolAddress((void**)&woH,  g_woH);
    cudaGetSymbolAddress((void**)&w1H,  g_w1H);
    cudaGetSymbolAddress((void**)&w2H,  g_w2H);
    cudaGetSymbolAddress((void**)&wlmH, g_wlmH);

    cudaFuncSetAttribute(gemm_h<false, true, false>,
                         cudaFuncAttributeMaxDynamicSharedMemorySize, GEMM_SMEM);
    cudaFuncSetAttribute(gemm_h<true, true, false>,
                         cudaFuncAttributeMaxDynamicSharedMemorySize, GEMM_SMEM);
    cudaFuncSetAttribute(gemm_h<false, false, false>,
                         cudaFuncAttributeMaxDynamicSharedMemorySize, GEMM_SMEM);
    cudaFuncSetAttribute(gemm_h<false, false, true>,
                         cudaFuncAttributeMaxDynamicSharedMemorySize, GEMM_SMEM);
    cudaFuncSetAttribute(attn_mma,
                         cudaFuncAttributeMaxDynamicSharedMemorySize, ATTN_SMEM);

    round_weights<<<dim3(N_FF / 8 / 256, 7), 256>>>(
        wq, wk, wv, wo, w1, w2, wlm, wqkvH, woH, w1H, w2H, wlmH);
    embed_kernel<<<BT, 256>>>(idx, tok, pos, x);

    const dim3 gQKV(C3 / 128, BT / 128);       // 384
    const dim3 gCCs(Cn / 128, BT / 128, 2);    // 256 (split-K atomic)
    const dim3 gCF(Fn / 128, BT / 128);        // 512
    const dim3 gCV(Vn / 128, BT / 128);        // 4000
    const dim3 gAttn(Tn / 128, Hn, Bn);        // 4 x 16 x 4 = 256
    const int  gLN = BT / 8;

    for (int l = 0; l < Ln; l++) {
        const __half* wqkvl = wqkvH + (size_t)l * Cn * C3;
        const __half* woHl = woH + (size_t)l * Cn * Cn;
        const float* bol  = bo + (size_t)l * Cn;
        const __half* w1Hl = w1H + (size_t)l * Cn * Fn;
        const float* b1l  = b1 + (size_t)l * Fn;
        const __half* w2Hl = w2H + (size_t)l * Fn * Cn;
        const float* b2l  = b2 + (size_t)l * Cn;

        ln_kernel<<<gLN, 256>>>(x, ln1g + l * Cn, ln1b + l * Cn, xn);
        gemm_h<false, true, false><<<gQKV, 128, GEMM_SMEM>>>(
            xn, wqkvl, nullptr, nullptr, qkv, C3, Cn);
        attn_mma<<<gAttn, 256, ATTN_SMEM>>>(qkv, y);
        gemm_h<false, false, true><<<gCCs, 128, GEMM_SMEM>>>(
            y, woHl, bol, nullptr, x, Cn, Cn);

        ln_kernel<<<gLN, 256>>>(x, ln2g + l * Cn, ln2b + l * Cn, xn);
        gemm_h<true, true, false><<<gCF, 128, GEMM_SMEM>>>(
            xn, w1Hl, b1l, nullptr, h, Fn, Cn);
        gemm_h<false, false, true><<<gCCs, 128, GEMM_SMEM>>>(
            h, w2Hl, b2l, nullptr, x, Cn, Fn);
    }

    ln_kernel<<<gLN, 256>>>(x, lnfg, lnfb, xn);
    gemm_h<false, false, false><<<gCV, 128, GEMM_SMEM>>>(
        xn, wlmH, nullptr, nullptr, out, Vn, Cn);
}

// round 16
// speedup vs baseline: 1.0263x; 1.0263x over previous
#include <cuda_runtime.h>
#include <cuda_fp16.h>
#include <cstdint>
#include <math.h>

// GPT forward: B=4, T=512, L=12, C=1024, H=16, HD=64, F=4096, V=32000
#define Bn   4
#define Tn   512
#define Ln   12
#define Cn   1024
#define Hn   16
#define HDn  64
#define Fn   4096
#define Vn   32000
#define BT   (Bn * Tn)          // 2048
#define C3   (3 * Cn)           // 3072

// ---------------- static scratch (no allocations allowed) ----------------
__device__ float  g_x  [BT * Cn];            // residual stream (fp32)
__device__ __half g_xn [BT * Cn];
__device__ __half g_qkv[BT * C3];
__device__ __half g_y  [BT * Cn];
__device__ __half g_h  [BT * Fn];
__device__ __half g_wqkvH[(size_t)Ln * Cn * C3];
__device__ __half g_woH[Ln * Cn * Cn];
__device__ __half g_w1H[Ln * Cn * Fn];
__device__ __half g_w2H[Ln * Fn * Cn];
__device__ __half g_wlmH[(size_t)Vn * Cn];

__device__ __forceinline__ uint32_t smem_u32(const void* p) {
    uint32_t a;
    asm("{ .reg .u64 t; cvta.to.shared.u64 t, %1; cvt.u32.u64 %0, t; }"
        : "=r"(a) : "l"(p));
    return a;
}
__device__ __forceinline__ void cp16(void* s, const void* g) {
    asm volatile("cp.async.cg.shared.global [%0], [%1], 16;"
                 :: "r"(smem_u32(s)), "l"(g) : "memory");
}
#define CP_COMMIT() asm volatile("cp.async.commit_group;" ::: "memory")
#define CP_WAIT1()  asm volatile("cp.async.wait_group 1;" ::: "memory")
#define CP_WAIT0()  asm volatile("cp.async.wait_group 0;" ::: "memory")

#define MMA_F16(acc, a, b0, b1) \
    asm volatile( \
        "mma.sync.aligned.m16n8k16.row.col.f32.f16.f16.f32 " \
        "{%0,%1,%2,%3}, {%4,%5,%6,%7}, {%8,%9}, {%0,%1,%2,%3};" \
        : "+f"((acc)[0]), "+f"((acc)[1]), "+f"((acc)[2]), "+f"((acc)[3]) \
        : "r"((a)[0]), "r"((a)[1]), "r"((a)[2]), "r"((a)[3]), \
          "r"(b0), "r"(b1))

// ---------------- weight rounding / packing to fp16 (exact grids) --------
#define N_QKVO (Ln * Cn * Cn)
#define N_FF   (Ln * Cn * Fn)
#define N_LM   ((size_t)Vn * Cn)

__device__ __forceinline__ void round8(const float* in, __half* out,
                                       size_t i, size_t oi) {
    float4 v0 = *(const float4*)(in + i);
    float4 v1 = *(const float4*)(in + i + 4);
    __half2 h[4];
    h[0] = __floats2half2_rn(v0.x, v0.y);
    h[1] = __floats2half2_rn(v0.z, v0.w);
    h[2] = __floats2half2_rn(v1.x, v1.y);
    h[3] = __floats2half2_rn(v1.z, v1.w);
    *(uint4*)(out + oi) = *(uint4*)h;
}

// y = 0..3: wq,wk,wv (packed into wqkvH), wo
__global__ void round_qkvo(const float* wq, const float* wk, const float* wv,
                           const float* wo, __half* wqkvH, __half* woH) {
    size_t i = ((size_t)blockIdx.x * 256 + threadIdx.x) * 8;
    int sel = blockIdx.y;
    if (sel == 3) {
        round8(wo, woH, i, i);
    } else {
        const float* in = (sel == 0) ? wq : (sel == 1) ? wk : wv;
        size_t l = i / (Cn * Cn);
        size_t rem = i - l * Cn * Cn;
        size_t kk = rem / Cn, nn = rem % Cn;
        size_t oi = (l * Cn + kk) * C3 + (size_t)sel * Cn + nn;
        round8(in, wqkvH, i, oi);
    }
}
// y = 0..1: w1, w2
__global__ void round_ff(const float* w1, const float* w2,
                         __half* w1H, __half* w2H) {
    size_t i = ((size_t)blockIdx.x * 256 + threadIdx.x) * 8;
    if (blockIdx.y == 0) round8(w1, w1H, i, i);
    else                 round8(w2, w2H, i, i);
}
__global__ void round_lm(const float* wlm, __half* wlmH) {
    size_t i = ((size_t)blockIdx.x * 256 + threadIdx.x) * 8;
    round8(wlm, wlmH, i, i);
}

// ---------------- embedding ----------------
__global__ void embed_kernel(const int* __restrict__ idx,
                             const float* __restrict__ tok,
                             const float* __restrict__ pos,
                             float* __restrict__ x) {
    int row = blockIdx.x;
    int t = row & (Tn - 1);
    int token = idx[row];
    const float* tp = tok + (size_t)token * Cn;
    const float* pp = pos + (size_t)t * Cn;
    float* xp = x + (size_t)row * Cn;
    for (int c = threadIdx.x; c < Cn; c += 256)
        xp[c] = tp[c] + pp[c];
}

// ---------------- layernorm: warp per row, shuffle reductions ------------
__global__ __launch_bounds__(256)
void ln_kernel(const float* __restrict__ in,
               const float* __restrict__ g,
               const float* __restrict__ b,
               __half* __restrict__ out) {
    const int lane = threadIdx.x & 31;
    const int row = blockIdx.x * 8 + (threadIdx.x >> 5);
    const float* p = in + (size_t)row * Cn;
    float v[32];
    float s = 0.f, sq = 0.f;
    #pragma unroll
    for (int k = 0; k < 32; k++) {
        v[k] = p[lane + 32 * k];
        s += v[k]; sq += v[k] * v[k];
    }
    #pragma unroll
    for (int o = 16; o > 0; o >>= 1) {
        s  += __shfl_xor_sync(0xffffffffu, s,  o);
        sq += __shfl_xor_sync(0xffffffffu, sq, o);
    }
    const float mean = s * (1.f / Cn);
    const float var  = sq * (1.f / Cn) - mean * mean;
    const float inv  = rsqrtf(var + 1e-5f);
    __half* op = out + (size_t)row * Cn;
    #pragma unroll
    for (int k = 0; k < 32; k++) {
        int c = lane + 32 * k;
        op[c] = __float2half((v[k] - mean) * inv * g[c] + b[c]);
    }
}

// ---------------- fp16 mma GEMM: CTA 128x128, 4 warps, BK=64, 3-stage ----
// SAFE pipeline: prologue stages 0,1; wait_group 1; compute it%3; prefetch
// (it+2)%3 (readers drained by this iteration's barrier).
#define APAD2 72
#define BPADh 136
#define ASZ2  (128 * APAD2)
#define BSZ2  (64 * BPADh)
#define STAGE2 (ASZ2 + BSZ2)
#define GEMM_SMEM (3 * STAGE2 * 2)       // 107520 bytes

template<bool RELU, bool OUTH, bool ATOMIC>
__global__ __launch_bounds__(128, 2)
void gemm_h(const __half* __restrict__ A, const __half* __restrict__ B,
            const float* __restrict__ bias, const float* __restrict__ res,
            void* __restrict__ Cout, int N, int K) {
    extern __shared__ __half smh[];
    const int tid = threadIdx.x;
    const int lane = tid & 31, wid = tid >> 5;
    const int warp_m = (wid & 1) << 6;
    const int warp_n = (wid >> 1) << 6;
    const int m0 = blockIdx.y * 128;
    const int n0 = blockIdx.x * 128;
    const int Ksub = K / gridDim.z;
    const int koff = blockIdx.z * Ksub;

    const __half* aptr[8]; int saoff[8];
    const __half* bptr[8]; int sboff[8];
    #pragma unroll
    for (int j = 0; j < 8; j++) {
        int ia = j * 128 + tid;
        int ar = ia >> 3, ac = (ia & 7) << 3;
        aptr[j] = A + (size_t)(m0 + ar) * K + koff + ac;
        saoff[j] = ar * APAD2 + ac;
        int bk = ia >> 4, bc = (ia & 15) << 3;
        bptr[j] = B + (size_t)(koff + bk) * N + n0 + bc;
        sboff[j] = bk * BPADh + bc;
    }

    const int nk = Ksub >> 6;

    #pragma unroll
    for (int s = 0; s < 2; s++) {
        __half* As = smh + s * STAGE2;
        __half* Bs = As + ASZ2;
        const int kk = s << 6;
        #pragma unroll
        for (int j = 0; j < 8; j++) {
            cp16(As + saoff[j], aptr[j] + kk);
            cp16(Bs + sboff[j], bptr[j] + (size_t)kk * N);
        }
        CP_COMMIT();
    }

    float acc[4][8][4];
    #pragma unroll
    for (int mi = 0; mi < 4; mi++)
        #pragma unroll
        for (int ni = 0; ni < 8; ni++)
            #pragma unroll
            for (int r = 0; r < 4; r++) acc[mi][ni][r] = 0.f;

    const int a_i = lane >> 3;
    const int arow_lane = ((a_i & 1) << 3) + (lane & 7);
    const int acol_lane = (a_i >> 1) << 3;
    const int vb_k = (lane & 7) + ((lane >> 3) & 1) * 8;
    const int vb_n = ((lane >> 4) & 1) * 8;

    int rs = 0, ws = 2;
    for (int it = 0; it < nk; ++it) {
        if (it + 1 < nk) CP_WAIT1(); else CP_WAIT0();
        __syncthreads();

        const __half* Ac = smh + rs * STAGE2;
        const __half* Bc = Ac + ASZ2;
        #pragma unroll
        for (int ks = 0; ks < 4; ks++) {
            const int kb = ks << 4;
            uint32_t af[4][4];
            #pragma unroll
            for (int mi = 0; mi < 4; mi++) {
                int row = warp_m + mi * 16 + arow_lane;
                uint32_t ad = smem_u32(Ac + row * APAD2 + kb + acol_lane);
                asm volatile("ldmatrix.sync.aligned.m8n8.x4.shared.b16 "
                             "{%0,%1,%2,%3}, [%4];"
                             : "=r"(af[mi][0]), "=r"(af[mi][1]),
                               "=r"(af[mi][2]), "=r"(af[mi][3]) : "r"(ad));
            }
            #pragma unroll
            for (int nj = 0; nj < 4; nj++) {
                uint32_t bv[4];
                uint32_t bd = smem_u32(Bc + (kb + vb_k) * BPADh
                                       + warp_n + nj * 16 + vb_n);
                asm volatile("ldmatrix.sync.aligned.m8n8.x4.trans.shared.b16 "
                             "{%0,%1,%2,%3}, [%4];"
                             : "=r"(bv[0]), "=r"(bv[1]), "=r"(bv[2]), "=r"(bv[3])
                             : "r"(bd));
                #pragma unroll
                for (int mi = 0; mi < 4; mi++) {
                    MMA_F16(acc[mi][nj * 2],     af[mi], bv[0], bv[1]);
                    MMA_F16(acc[mi][nj * 2 + 1], af[mi], bv[2], bv[3]);
                }
            }
        }

        if (it + 2 < nk) {
            const int kk = (it + 2) << 6;
            __half* As = smh + ws * STAGE2;
            __half* Bs = As + ASZ2;
            #pragma unroll
            for (int j = 0; j < 8; j++) {
                cp16(As + saoff[j], aptr[j] + kk);
                cp16(Bs + sboff[j], bptr[j] + (size_t)kk * N);
            }
        }
        CP_COMMIT();

        rs = (rs == 2) ? 0 : rs + 1;
        ws = (ws == 2) ? 0 : ws + 1;
    }

    const bool addb = (bias != nullptr) && (!ATOMIC || blockIdx.z == 0);
    #pragma unroll
    for (int mi = 0; mi < 4; mi++) {
        int row = m0 + warp_m + mi * 16 + (lane >> 2);
        #pragma unroll
        for (int ni = 0; ni < 8; ni++) {
            int col = n0 + warp_n + ni * 8 + ((lane & 3) << 1);
            float v0 = acc[mi][ni][0], v1 = acc[mi][ni][1];
            float v2 = acc[mi][ni][2], v3 = acc[mi][ni][3];
            if (addb) {
                float b0 = bias[col], b1 = bias[col + 1];
                v0 += b0; v1 += b1; v2 += b0; v3 += b1;
            }
            if (RELU) {
                v0 = fmaxf(v0, 0.f); v1 = fmaxf(v1, 0.f);
                v2 = fmaxf(v2, 0.f); v3 = fmaxf(v3, 0.f);
            }
            if (ATOMIC) {
                float* Cp = (float*)Cout;
                atomicAdd(Cp + (size_t)row * N + col,       v0);
                atomicAdd(Cp + (size_t)row * N + col + 1,   v1);
                atomicAdd(Cp + (size_t)(row + 8) * N + col,     v2);
                atomicAdd(Cp + (size_t)(row + 8) * N + col + 1, v3);
            } else if (OUTH) {
                __half* Cp = (__half*)Cout;
                *(__half2*)(Cp + (size_t)row * N + col) = __floats2half2_rn(v0, v1);
                *(__half2*)(Cp + (size_t)(row + 8) * N + col) = __floats2half2_rn(v2, v3);
            } else {
                float* Cp = (float*)Cout;
                if (res) {
                    const float2 r0 = *(const float2*)(res + (size_t)row * N + col);
                    const float2 r1 = *(const float2*)(res + (size_t)(row + 8) * N + col);
                    v0 += r0.x; v1 += r0.y; v2 += r1.x; v3 += r1.y;
                }
                *(float2*)(Cp + (size_t)row * N + col) = make_float2(v0, v1);
                *(float2*)(Cp + (size_t)(row + 8) * N + col) = make_float2(v2, v3);
            }
        }
    }
}

// ---------------- tensor-core flash attention (64 rows, cp.async) --------
#define QP 72

__global__ __launch_bounds__(128)
void attn_mma(const __half* __restrict__ qkv, __half* __restrict__ y) {
    const int tt = blockIdx.x, h = blockIdx.y, b = blockIdx.z;
    const int tid = threadIdx.x, lane = tid & 31, wid = tid >> 5;
    __shared__ __align__(16) __half sQ[64 * QP];
    __shared__ __align__(16) __half sK[2][64 * QP];
    __shared__ __align__(16) __half sV[2][64 * QP];
    const size_t base = (size_t)b * Tn * C3 + (size_t)h * HDn;
    const int t0 = tt * 64;

    #pragma unroll
    for (int j = 0; j < 4; j++) {
        int i = j * 128 + tid;
        int r = i >> 3, c = (i & 7) << 3;
        size_t g = base + (size_t)(t0 + r) * C3 + c;
        cp16(sQ + r * QP + c, qkv + g);
    }
    #pragma unroll
    for (int j = 0; j < 4; j++) {
        int i = j * 128 + tid;
        int r = i >> 3, c = (i & 7) << 3;
        size_t g = base + (size_t)r * C3 + c;
        cp16(sK[0] + r * QP + c, qkv + g + Cn);
        cp16(sV[0] + r * QP + c, qkv + g + 2 * Cn);
    }
    CP_COMMIT();
    CP_WAIT0();
    __syncthreads();

    const int a_i = lane >> 3;
    const int arow = ((a_i & 1) << 3) + (lane & 7);
    const int acol = (a_i >> 1) << 3;
    uint32_t qA[4][4];
    #pragma unroll
    for (int kt = 0; kt < 4; kt++) {
        uint32_t ad = smem_u32(sQ + (wid * 16 + arow) * QP + kt * 16 + acol);
        asm volatile("ldmatrix.sync.aligned.m8n8.x4.shared.b16 "
                     "{%0,%1,%2,%3}, [%4];"
                     : "=r"(qA[kt][0]), "=r"(qA[kt][1]),
                       "=r"(qA[kt][2]), "=r"(qA[kt][3]) : "r"(ad));
    }

    float o[8][4];
    #pragma unroll
    for (int ni = 0; ni < 8; ni++)
        #pragma unroll
        for (int r = 0; r < 4; r++) o[ni][r] = 0.f;
    float m0 = -1e30f, m1 = -1e30f, l0 = 0.f, l1 = 0.f;

    const int c_lane = (lane & 3) << 1;
    const int tr0 = t0 + wid * 16 + (lane >> 2);

    const int kb_n = (lane & 7) + ((lane >> 4) & 1) * 8;
    const int kb_k = ((lane >> 3) & 1) * 8;
    const int vb_k = (lane & 7) + ((lane >> 3) & 1) * 8;
    const int vb_n = ((lane >> 4) & 1) * 8;

    for (int st = 0; st <= tt; ++st) {
        CP_WAIT0();
        __syncthreads();

        if (st + 1 <= tt) {
            const int s1 = (st + 1) * 64;
            __half* dK = sK[(st + 1) & 1];
            __half* dV = sV[(st + 1) & 1];
            #pragma unroll
            for (int j = 0; j < 4; j++) {
                int i = j * 128 + tid;
                int r = i >> 3, c = (i & 7) << 3;
                size_t g = base + (size_t)(s1 + r) * C3 + c;
                cp16(dK + r * QP + c, qkv + g + Cn);
                cp16(dV + r * QP + c, qkv + g + 2 * Cn);
            }
        }
        CP_COMMIT();

        const __half* cK = sK[st & 1];
        const __half* cV = sV[st & 1];
        const int s0 = st * 64;

        float s[8][4];
        #pragma unroll
        for (int ni = 0; ni < 8; ni++)
            #pragma unroll
            for (int r = 0; r < 4; r++) s[ni][r] = 0.f;

        #pragma unroll
        for (int kt = 0; kt < 4; kt++) {
            #pragma unroll
            for (int nj = 0; nj < 4; nj++) {
                uint32_t bf[4];
                uint32_t bd = smem_u32(cK + (nj * 16 + kb_n) * QP + kt * 16 + kb_k);
                asm volatile("ldmatrix.sync.aligned.m8n8.x4.shared.b16 "
                             "{%0,%1,%2,%3}, [%4];"
                             : "=r"(bf[0]), "=r"(bf[1]), "=r"(bf[2]), "=r"(bf[3])
                             : "r"(bd));
                MMA_F16(s[nj * 2],     qA[kt], bf[0], bf[1]);
                MMA_F16(s[nj * 2 + 1], qA[kt], bf[2], bf[3]);
            }
        }

        #pragma unroll
        for (int ni = 0; ni < 8; ni++) {
            s[ni][0] *= 0.125f; s[ni][1] *= 0.125f;
            s[ni][2] *= 0.125f; s[ni][3] *= 0.125f;
        }
        if (st == tt) {
            #pragma unroll
            for (int ni = 0; ni < 8; ni++) {
                int sc = s0 + ni * 8 + c_lane;
                if (sc     > tr0)     s[ni][0] = -1e30f;
                if (sc + 1 > tr0)     s[ni][1] = -1e30f;
                if (sc     > tr0 + 8) s[ni][2] = -1e30f;
                if (sc + 1 > tr0 + 8) s[ni][3] = -1e30f;
            }
        }

        float tm0 = m0, tm1 = m1;
        #pragma unroll
        for (int ni = 0; ni < 8; ni++) {
            tm0 = fmaxf(tm0, fmaxf(s[ni][0], s[ni][1]));
            tm1 = fmaxf(tm1, fmaxf(s[ni][2], s[ni][3]));
        }
        tm0 = fmaxf(tm0, __shfl_xor_sync(0xffffffffu, tm0, 1));
        tm0 = fmaxf(tm0, __shfl_xor_sync(0xffffffffu, tm0, 2));
        tm1 = fmaxf(tm1, __shfl_xor_sync(0xffffffffu, tm1, 1));
        tm1 = fmaxf(tm1, __shfl_xor_sync(0xffffffffu, tm1, 2));
        if (tm0 > m0) {
            float sc_ = __expf(m0 - tm0);
            l0 *= sc_;
            #pragma unroll
            for (int ni = 0; ni < 8; ni++) { o[ni][0] *= sc_; o[ni][1] *= sc_; }
            m0 = tm0;
        }
        if (tm1 > m1) {
            float sc_ = __expf(m1 - tm1);
            l1 *= sc_;
            #pragma unroll
            for (int ni = 0; ni < 8; ni++) { o[ni][2] *= sc_; o[ni][3] *= sc_; }
            m1 = tm1;
        }
        #pragma unroll
        for (int ni = 0; ni < 8; ni++) {
            s[ni][0] = __expf(s[ni][0] - m0);
            s[ni][1] = __expf(s[ni][1] - m0);
            s[ni][2] = __expf(s[ni][2] - m1);
            s[ni][3] = __expf(s[ni][3] - m1);
            l0 += s[ni][0] + s[ni][1];
            l1 += s[ni][2] + s[ni][3];
        }

        uint32_t aP[4][4];
        #pragma unroll
        for (int kt = 0; kt < 4; kt++) {
            __half2 h0 = __floats2half2_rn(s[2 * kt][0],     s[2 * kt][1]);
            __half2 h1 = __floats2half2_rn(s[2 * kt][2],     s[2 * kt][3]);
            __half2 h2v = __floats2half2_rn(s[2 * kt + 1][0], s[2 * kt + 1][1]);
            __half2 h3 = __floats2half2_rn(s[2 * kt + 1][2], s[2 * kt + 1][3]);
            aP[kt][0] = *(uint32_t*)&h0;
            aP[kt][1] = *(uint32_t*)&h1;
            aP[kt][2] = *(uint32_t*)&h2v;
            aP[kt][3] = *(uint32_t*)&h3;
        }

        #pragma unroll
        for (int kt = 0; kt < 4; kt++) {
            #pragma unroll
            for (int nj = 0; nj < 4; nj++) {
                uint32_t bv[4];
                uint32_t bd = smem_u32(cV + (kt * 16 + vb_k) * QP + nj * 16 + vb_n);
                asm volatile("ldmatrix.sync.aligned.m8n8.x4.trans.shared.b16 "
                             "{%0,%1,%2,%3}, [%4];"
                             : "=r"(bv[0]), "=r"(bv[1]), "=r"(bv[2]), "=r"(bv[3])
                             : "r"(bd));
                MMA_F16(o[nj * 2],     aP[kt], bv[0], bv[1]);
                MMA_F16(o[nj * 2 + 1], aP[kt], bv[2], bv[3]);
            }
        }
    }

    l0 += __shfl_xor_sync(0xffffffffu, l0, 1);
    l0 += __shfl_xor_sync(0xffffffffu, l0, 2);
    l1 += __shfl_xor_sync(0xffffffffu, l1, 1);
    l1 += __shfl_xor_sync(0xffffffffu, l1, 2);
    const float inv0 = 1.f / l0, inv1 = 1.f / l1;
    const size_t ybase = (size_t)b * Tn * Cn + (size_t)h * HDn;
    #pragma unroll
    for (int ni = 0; ni < 8; ni++) {
        int d = ni * 8 + c_lane;
        *(__half2*)(y + ybase + (size_t)tr0 * Cn + d) =
            __floats2half2_rn(o[ni][0] * inv0, o[ni][1] * inv0);
        *(__half2*)(y + ybase + (size_t)(tr0 + 8) * Cn + d) =
            __floats2half2_rn(o[ni][2] * inv1, o[ni][3] * inv1);
    }
}

// ---------------- launch ----------------
extern "C" void kernel_launch(void* const* d_in, const int* in_sizes, int n_in,
                              void* d_out, int out_size) {
    const int*   idx   = (const int*)  d_in[0];
    const float* tok   = (const float*)d_in[1];
    const float* pos   = (const float*)d_in[2];
    const float* wq    = (const float*)d_in[3];
    const float* wk    = (const float*)d_in[4];
    const float* wv    = (const float*)d_in[5];
    const float* wo    = (const float*)d_in[6];
    const float* bo    = (const float*)d_in[7];
    const float* ln1g  = (const float*)d_in[8];
    const float* ln1b  = (const float*)d_in[9];
    const float* ln2g  = (const float*)d_in[10];
    const float* ln2b  = (const float*)d_in[11];
    const float* w1    = (const float*)d_in[12];
    const float* b1    = (const float*)d_in[13];
    const float* w2    = (const float*)d_in[14];
    const float* b2    = (const float*)d_in[15];
    const float* lnfg  = (const float*)d_in[16];
    const float* lnfb  = (const float*)d_in[17];
    const float* wlm   = (const float*)d_in[18];
    float* out = (float*)d_out;

    float *x;
    __half *xn, *qkv, *y, *h;
    __half *wqkvH, *woH, *w1H, *w2H, *wlmH;
    cudaGetSymbolAddress((void**)&x,   g_x);
    cudaGetSymbolAddress((void**)&xn,  g_xn);
    cudaGetSymbolAddress((void**)&qkv, g_qkv);
    cudaGetSymbolAddress((void**)&y,   g_y);
    cudaGetSymbolAddress((void**)&h,   g_h);
    cudaGetSymbolAddress((void**)&wqkvH, g_wqkvH);
    cudaGetSymbolAddress((void**)&woH,  g_woH);
    cudaGetSymbolAddress((void**)&w1H,  g_w1H);
    cudaGetSymbolAddress((void**)&w2H,  g_w2H);
    cudaGetSymbolAddress((void**)&wlmH, g_wlmH);

    cudaFuncSetAttribute(gemm_h<false, true, false>,
                         cudaFuncAttributeMaxDynamicSharedMemorySize, GEMM_SMEM);
    cudaFuncSetAttribute(gemm_h<true, true, false>,
                         cudaFuncAttributeMaxDynamicSharedMemorySize, GEMM_SMEM);
    cudaFuncSetAttribute(gemm_h<false, false, false>,
                         cudaFuncAttributeMaxDynamicSharedMemorySize, GEMM_SMEM);
    cudaFuncSetAttribute(gemm_h<false, false, true>,
                         cudaFuncAttributeMaxDynamicSharedMemorySize, GEMM_SMEM);

    // weight rounding: exactly-sized grids (all counts divide 2048)
    round_qkvo<<<dim3(N_QKVO / 2048, 4), 256>>>(wq, wk, wv, wo, wqkvH, woH);
    round_ff<<<dim3(N_FF / 2048, 2), 256>>>(w1, w2, w1H, w2H);
    round_lm<<<dim3((unsigned)(N_LM / 2048), 1), 256>>>(wlm, wlmH);
    embed_kernel<<<BT, 256>>>(idx, tok, pos, x);

    const dim3 gQKV(C3 / 128, BT / 128);       // 384
    const dim3 gCCs(Cn / 128, BT / 128, 2);    // 256 (split-K atomic)
    const dim3 gCF(Fn / 128, BT / 128);        // 512
    const dim3 gCV(Vn / 128, BT / 128);        // 4000
    const dim3 gAttn(Tn / 64, Hn, Bn);         // 8 x 16 x 4
    const int  gLN = BT / 8;

    for (int l = 0; l < Ln; l++) {
        const __half* wqkvl = wqkvH + (size_t)l * Cn * C3;
        const __half* woHl = woH + (size_t)l * Cn * Cn;
        const float* bol  = bo + (size_t)l * Cn;
        const __half* w1Hl = w1H + (size_t)l * Cn * Fn;
        const float* b1l  = b1 + (size_t)l * Fn;
        const __half* w2Hl = w2H + (size_t)l * Fn * Cn;
        const float* b2l  = b2 + (size_t)l * Cn;

        ln_kernel<<<gLN, 256>>>(x, ln1g + l * Cn, ln1b + l * Cn, xn);
        gemm_h<false, true, false><<<gQKV, 128, GEMM_SMEM>>>(
            xn, wqkvl, nullptr, nullptr, qkv, C3, Cn);
        attn_mma<<<gAttn, 128>>>(qkv, y);
        gemm_h<false, false, true><<<gCCs, 128, GEMM_SMEM>>>(
            y, woHl, bol, nullptr, x, Cn, Cn);

        ln_kernel<<<gLN, 256>>>(x, ln2g + l * Cn, ln2b + l * Cn, xn);
        gemm_h<true, true, false><<<gCF, 128, GEMM_SMEM>>>(
            xn, w1Hl, b1l, nullptr, h, Fn, Cn);
        gemm_h<false, false, true><<<gCCs, 128, GEMM_SMEM>>>(
            h, w2Hl, b2l, nullptr, x, Cn, Fn);
    }

    ln_kernel<<<gLN, 256>>>(x, lnfg, lnfb, xn);
    gemm_h<false, false, false><<<gCV, 128, GEMM_SMEM>>>(
        xn, wlmH, nullptr, nullptr, out, Vn, Cn);
}